// round 12
// baseline (speedup 1.0000x reference)
#include <cuda_runtime.h>
#include <cuda_bf16.h>

// Problem constants: B=16, N=1024, M=4096, D=64
#define BB 16
#define NN 1024
#define MM 4096
#define DD 64
#define INF_BITS 0x7f800000u

// ---------------- device scratch (no cudaMalloc allowed) ----------------
__device__ float g_C[(size_t)BB * NN * MM];                 // 256 MB cost matrix
__device__ float g_x2[BB * NN];
__device__ float g_y2[BB * MM];
// packed moves: 4 cells per byte (2 bits each), row stride = MM/4 = 1024 bytes.
__device__ unsigned char g_mv[(size_t)BB * NN * (MM / 4) + 128];
// inter-CTA boundary handoff: 3 interfaces per batch, one word per row
__device__ unsigned g_bnd[BB][3][NN];
// per-(batch,128-row-block) readiness counters (gemm colblocks done, target 32)
__device__ unsigned g_rdy[BB][NN / 128];
// per-CTA last-row argmin partials (4 CTAs per batch)
__device__ float g_pv[BB][4];
__device__ int g_pi[BB][4];

__device__ __forceinline__ unsigned ldcg_u32(const unsigned* p) {
    unsigned v;
    asm volatile("ld.global.cg.u32 %0, [%1];" : "=r"(v) : "l"(p));
    return v;
}
__device__ __forceinline__ unsigned ldacq_u32(const unsigned* p) {
    unsigned v;
    asm volatile("ld.global.acquire.gpu.u32 %0, [%1];" : "=r"(v) : "l"(p));
    return v;
}
__device__ __forceinline__ void stcg_u32(unsigned* p, unsigned v) {
    asm volatile("st.global.cg.u32 [%0], %1;" :: "l"(p), "r"(v));
}
__device__ __forceinline__ void cpasync16(void* smem_dst, const void* gsrc) {
    unsigned saddr;
    asm("{ .reg .u64 t; cvta.to.shared.u64 t, %1; cvt.u32.u64 %0, t; }"
        : "=r"(saddr) : "l"(smem_dst));
    asm volatile("cp.async.cg.shared.global [%0], [%1], 16;"
                 :: "r"(saddr), "l"(gsrc) : "memory");
}
#define CP_COMMIT() asm volatile("cp.async.commit_group;" ::: "memory")
#define CP_WAIT6()  asm volatile("cp.async.wait_group 6;" ::: "memory")

// ---------------- kernel 0a: row squared norms ----------------
__global__ void norms_kernel(const float* __restrict__ x, const float* __restrict__ y) {
    int idx = blockIdx.x * blockDim.x + threadIdx.x;
    const float* src;
    float* dst;
    if (idx < BB * NN) {
        src = x + (size_t)idx * DD;
        dst = g_x2 + idx;
    } else if (idx < BB * NN + BB * MM) {
        int k = idx - BB * NN;
        src = y + (size_t)k * DD;
        dst = g_y2 + k;
    } else {
        return;
    }
    float s = 0.f;
#pragma unroll
    for (int q = 0; q < DD / 4; q++) {
        float4 v = *(const float4*)(src + q * 4);
        s += v.x * v.x + v.y * v.y + v.z * v.z + v.w * v.w;
    }
    *dst = s;
}

// ---------------- kernel 0b: reset sentinels + readiness flags ----------------
__global__ void init_bnd_kernel() {
    int i = blockIdx.x * blockDim.x + threadIdx.x;
    if (i < BB * 3 * NN) ((unsigned*)g_bnd)[i] = INF_BITS;
    if (i < BB * (NN / 128)) ((unsigned*)g_rdy)[i] = 0u;
}

// ---------------- fused kernel: GEMM producer + DTW consumer ----------------
// blockIdx 0..63            : DTW CTAs (4 per batch) — first wave, all resident
// blockIdx 64..64+4095      : GEMM CTAs, rowblock-major order so row-block 0 of
//                             every batch completes first (~2 waves).
// Producer: gemm CTA stores its 128x128 C tile, __threadfence, atomicAdd on
// g_rdy[b][rowblock]. Consumer: dtw checks g_rdy with an acquire load before
// issuing the cp.async prefetch for a row in a not-yet-confirmed block (once
// per 128 rows).

union SmemU {
    struct {                                    // gemm view (32 KB)
        float Xs[32][128];
        float Ys[32][128];
    } g;
    struct {                                    // dtw view (~36.4 KB)
        unsigned sB[7][128];
        float4 sring[8][8][32];
        float sRv[8];
        int sRi[8];
    } d;
};

__device__ __forceinline__ void gemm_body(SmemU* smem, int g,
                                          const float* __restrict__ x,
                                          const float* __restrict__ y) {
    // g in [0, 4096): colblock fastest, then batch, rowblock slowest
    int cb = g & 31;
    int b = (g >> 5) & 15;
    int ry = g >> 9;
    int i0 = ry * 128;
    int j0 = cb * 128;
    float (*Xs)[128] = smem->g.Xs;
    float (*Ys)[128] = smem->g.Ys;
    const float* xb = x + (size_t)b * NN * DD;
    const float* yb = y + (size_t)b * MM * DD;
    int tid = threadIdx.x;
    int txc = tid & 15, tyc = tid >> 4;

    float acc[8][8];
#pragma unroll
    for (int a = 0; a < 8; a++)
#pragma unroll
        for (int c = 0; c < 8; c++) acc[a][c] = 0.f;

#pragma unroll
    for (int kt = 0; kt < DD; kt += 32) {
#pragma unroll
        for (int p = 0; p < 4; p++) {
            int idx = tid + p * 256;
            int q = idx & 7;
            int r = idx >> 3;
            float4 xv = *(const float4*)(xb + (size_t)(i0 + r) * DD + kt + q * 4);
            Xs[q * 4 + 0][r] = xv.x;
            Xs[q * 4 + 1][r] = xv.y;
            Xs[q * 4 + 2][r] = xv.z;
            Xs[q * 4 + 3][r] = xv.w;
            float4 yv = *(const float4*)(yb + (size_t)(j0 + r) * DD + kt + q * 4);
            Ys[q * 4 + 0][r] = yv.x;
            Ys[q * 4 + 1][r] = yv.y;
            Ys[q * 4 + 2][r] = yv.z;
            Ys[q * 4 + 3][r] = yv.w;
        }
        __syncthreads();
#pragma unroll
        for (int kk = 0; kk < 32; kk++) {
            float xf[8], yf[8];
            *(float4*)&xf[0] = *(const float4*)&Xs[kk][tyc * 4];
            *(float4*)&xf[4] = *(const float4*)&Xs[kk][64 + tyc * 4];
            *(float4*)&yf[0] = *(const float4*)&Ys[kk][txc * 4];
            *(float4*)&yf[4] = *(const float4*)&Ys[kk][64 + txc * 4];
#pragma unroll
            for (int mm = 0; mm < 8; mm++)
#pragma unroll
                for (int nn = 0; nn < 8; nn++)
                    acc[mm][nn] = fmaf(xf[mm], yf[nn], acc[mm][nn]);
        }
        __syncthreads();
    }

    float y2v[8];
    *(float4*)&y2v[0] = *(const float4*)(g_y2 + b * MM + j0 + txc * 4);
    *(float4*)&y2v[4] = *(const float4*)(g_y2 + b * MM + j0 + 64 + txc * 4);
#pragma unroll
    for (int mm = 0; mm < 8; mm++) {
        int row = i0 + ((mm < 4) ? (tyc * 4 + mm) : (64 + tyc * 4 + mm - 4));
        float x2v = g_x2[b * NN + row];
        float* crow = g_C + ((size_t)b * NN + row) * MM + j0;
        float4 v0, v1;
        v0.x = x2v + y2v[0] - 2.f * acc[mm][0];
        v0.y = x2v + y2v[1] - 2.f * acc[mm][1];
        v0.z = x2v + y2v[2] - 2.f * acc[mm][2];
        v0.w = x2v + y2v[3] - 2.f * acc[mm][3];
        v1.x = x2v + y2v[4] - 2.f * acc[mm][4];
        v1.y = x2v + y2v[5] - 2.f * acc[mm][5];
        v1.z = x2v + y2v[6] - 2.f * acc[mm][6];
        v1.w = x2v + y2v[7] - 2.f * acc[mm][7];
        *(float4*)(crow + txc * 4) = v0;
        *(float4*)(crow + 64 + txc * 4) = v1;
    }

    // publish: this (batch, rowblock) colblock is done
    __syncthreads();
    if (tid == 0) {
        __threadfence();
        atomicAdd(&g_rdy[b][ry], 1u);
    }
}

__device__ __forceinline__ void dtw_body(SmemU* smem, int cta) {
    const unsigned FULL = 0xffffffffu;
    const float INF = __uint_as_float(INF_BITS);
    int b = cta >> 2, r = cta & 3;
    int t = threadIdx.x, lane = t & 31, w = t >> 5;
    int chunk = 7 - w;                          // 0 = leftmost chunk of this CTA
    int colbase = r * 1024 + chunk * 128 + lane * 4;
    const float* Cp = g_C + (size_t)b * NN * MM + colbase;
    unsigned char* mvp = g_mv + (size_t)b * NN * (MM / 4) + (colbase >> 2);

    volatile unsigned (*sB)[128] = (volatile unsigned (*)[128])smem->d.sB;
    float4 (*sring)[32] = (float4 (*)[32])smem->d.sring[w];
    float* sRv = smem->d.sRv;
    int* sRi = smem->d.sRi;
    for (int q = t; q < 7 * 128; q += 256) ((volatile unsigned*)smem->d.sB)[q] = INF_BITS;
    __syncthreads();

    const bool gin = (w == 7 && r > 0);         // leftmost chunk consumes gmem boundary
    const bool gout = (w == 0 && r < 3);        // rightmost chunk produces gmem boundary
    const unsigned* gbi = gin ? &g_bnd[b][r - 1][0] : (const unsigned*)0;
    unsigned* gbo = gout ? &g_bnd[b][r][0] : (unsigned*)0;

    // ---- wait for C row-block 0 of this batch ----
    while (ldacq_u32(&g_rdy[b][0]) < 32u) {}
    int readyUpTo = 128;

    // ---- cp.async prologue: rows 0..5 in flight ----
#pragma unroll
    for (int k = 0; k < 6; k++) {
        cpasync16(&sring[k][lane], Cp + (size_t)k * MM);
        CP_COMMIT();
    }
    cpasync16(&sring[6][lane], Cp + 6 * (size_t)MM);
    CP_COMMIT();
    CP_WAIT6();

    // ---- row 0: D = C[0,:] ----
    float4 c4 = sring[0][lane];
    float pd[4] = {c4.x, c4.y, c4.z, c4.w};

    // acquire left boundary of row 0 (becomes prevB for row 1)
    float B = INF;
    if (w < 7) {
        unsigned vb;
        do { vb = sB[w][0]; } while (vb == INF_BITS);
        if (lane == 0) sB[w][0] = INF_BITS;
        B = __uint_as_float(vb);
    } else if (gin) {
        unsigned vb;
        do { vb = ldcg_u32(gbi + 0); } while (vb == INF_BITS);
        B = __uint_as_float(vb);
    }
    float prevB = B;

    // publish D[0][chunk_end]
    {
        float dend = __shfl_sync(FULL, pd[3], 31);
        if (lane == 31) {
            unsigned ob = __float_as_uint(dend);
            if (w > 0) sB[w - 1][0] = ob;
            else if (gout) stcg_u32(gbo + 0, ob);
        }
    }

    for (int i = 1; i < NN; i++) {
        // keep 6 C rows in flight; guard readiness once per 128 rows
        int q = i + 6;
        if (q < NN) {
            if (q >= readyUpTo) {
                while (ldacq_u32(&g_rdy[b][q >> 7]) < 32u) {}
                readyUpTo += 128;
            }
            cpasync16(&sring[q & 7][lane], Cp + (size_t)q * MM);
        }
        CP_COMMIT();
        CP_WAIT6();                              // rows <= i ready

        // eager inter-CTA boundary load: latency overlaps the scan below
        unsigned vb0 = INF_BITS;
        if (gin && lane == 0) vb0 = ldcg_u32(gbi + i);

        float4 cc = sring[i & 7][lane];
        float c[4] = {cc.x, cc.y, cc.z, cc.w};

        // pl = D[i-1][j-1]
        float pl0 = __shfl_up_sync(FULL, pd[3], 1);
        if (lane == 0) pl0 = prevB;
        float a[4];
        a[0] = fminf(pd[0], pl0) + c[0];
#pragma unroll
        for (int k = 1; k < 4; k++) a[k] = fminf(pd[k], pd[k - 1]) + c[k];

        // thread-local min-plus compose
        float Sl = c[0], Ml = a[0];
#pragma unroll
        for (int k = 1; k < 4; k++) {
            Sl += c[k];
            Ml = fminf(Ml + c[k], a[k]);
        }
        // warp inclusive min-plus pair scan (speculative w.r.t. boundary B)
        float iS = Sl, iM = Ml;
#pragma unroll
        for (int off = 1; off < 32; off <<= 1) {
            float oS = __shfl_up_sync(FULL, iS, off);
            float oM = __shfl_up_sync(FULL, iM, off);
            if (lane >= off) { iM = fminf(oM + iS, iM); iS = oS + iS; }
        }
        float eS = __shfl_up_sync(FULL, iS, 1);
        float eM = __shfl_up_sync(FULL, iM, 1);
        if (lane == 0) { eS = 0.f; eM = INF; }

        // acquire left boundary B = D[i][chunk_start-1]
        B = INF;
        if (w < 7) {
            unsigned vb;
            volatile unsigned* sl = &sB[w][i & 127];
            do { vb = *sl; } while (vb == INF_BITS);
            if (lane == 0) *sl = INF_BITS;
            B = __uint_as_float(vb);
        } else if (gin) {
            if (lane == 0) {
                while (vb0 == INF_BITS) vb0 = ldcg_u32(gbi + i);
            }
            vb0 = __shfl_sync(FULL, vb0, 0);
            B = __uint_as_float(vb0);
        }

        // publish own boundary ASAP (lane 31 holds the chunk totals).
        if (lane == 31) {
            float dend = fminf(B + iS, iM);
            unsigned ob = __float_as_uint(dend);
            if (w > 0) {
                volatile unsigned* so = &sB[w - 1][i & 127];
                while (*so != INF_BITS) {}       // back-pressure (depth-128 ring)
                *so = ob;
            } else if (gout) {
                stcg_u32(gbo + i, ob);
            }
        }

        // finalize with the carry applied
        float M_ex = fminf(B + eS, eM);         // == D[i][lane_start-1]
        float nd[4];
        float Mr = M_ex;
#pragma unroll
        for (int k = 0; k < 4; k++) {
            Mr = fminf(Mr + c[k], a[k]);
            nd[k] = Mr;
        }
        // move codes (dd = D[i-1][j-1], du = D[i-1][j], dl = D[i][j-1])
        unsigned pk = 0;
        float dl = M_ex, dd = pl0;
#pragma unroll
        for (int k = 0; k < 4; k++) {
            float du = pd[k];
            unsigned m = (du <= dl) ? 1u : 2u;
            if (dd <= du && dd <= dl) m = 0u;
            pk |= m << (2 * k);
            dd = du;
            dl = nd[k];
        }
        mvp[(size_t)i * (MM / 4)] = (unsigned char)pk;

        prevB = B;
#pragma unroll
        for (int k = 0; k < 4; k++) pd[k] = nd[k];
    }

    // ---- per-CTA argmin of last row (first index on exact ties) ----
    float bv = pd[0];
    int bi = colbase;
#pragma unroll
    for (int k = 1; k < 4; k++)
        if (pd[k] < bv) { bv = pd[k]; bi = colbase + k; }
#pragma unroll
    for (int off = 16; off > 0; off >>= 1) {
        float ov = __shfl_down_sync(FULL, bv, off);
        int oi = __shfl_down_sync(FULL, bi, off);
        if (ov < bv || (ov == bv && oi < bi)) { bv = ov; bi = oi; }
    }
    if (lane == 0) { sRv[w] = bv; sRi[w] = bi; }
    __syncthreads();
    if (t == 0) {
        float v = sRv[0]; int ix = sRi[0];
#pragma unroll
        for (int qq = 1; qq < 8; qq++)
            if (sRv[qq] < v || (sRv[qq] == v && sRi[qq] < ix)) { v = sRv[qq]; ix = sRi[qq]; }
        g_pv[b][r] = v;
        g_pi[b][r] = ix;
    }
}

__global__ void __launch_bounds__(256, 1) fused_kernel(const float* __restrict__ x,
                                                       const float* __restrict__ y) {
    __shared__ SmemU smem;
    int bid = blockIdx.x;
    if (bid < BB * 4) {
        dtw_body(&smem, bid);
    } else {
        gemm_body(&smem, bid - BB * 4, x, y);
    }
}

// ---------------- kernel 3: backtrack over packed moves ----------------
__global__ void __launch_bounds__(32) backtrack_kernel(const float* __restrict__ xt,
                                                       const float* __restrict__ yt,
                                                       float* __restrict__ out) {
    int b = blockIdx.x;
    int lane = threadIdx.x;
    __shared__ uint4 tile4[64][5];    // 64 rows x 80 bytes (20 words)
    __shared__ int syl[NN];
    __shared__ int sij[2];
    const unsigned* tw = (const unsigned*)tile4;
    const unsigned char* mvb = g_mv + (size_t)b * NN * (MM / 4);

    // final argmin across the 4 CTA partials (first global index on ties)
    if (lane == 0) {
        float bv = g_pv[b][0]; int bi = g_pi[b][0];
#pragma unroll
        for (int q = 1; q < 4; q++) {
            float v = g_pv[b][q]; int ix = g_pi[b][q];
            if (v < bv || (v == bv && ix < bi)) { bv = v; bi = ix; }
        }
        out[b] = bv;                  // dtw_cost
        syl[NN - 1] = bi;
        sij[0] = NN - 1; sij[1] = bi;
    }
    __syncwarp();
    int i = sij[0], j = sij[1];

    while (i > 0) {
        int r0 = i - 63; if (r0 < 1) r0 = 1;
        int wb0 = (j >> 4) - 15; if (wb0 < 0) wb0 = 0;
        wb0 &= ~3;                    // 16B-align the word window
#pragma unroll
        for (int p = 0; p < 10; p++) {
            int idx = lane + p * 32;  // 0..319
            int rr = idx / 5, q = idx - rr * 5;
            tile4[rr][q] = *(const uint4*)(mvb + (size_t)(r0 + rr) * (MM / 4) + wb0 * 4 + q * 16);
        }
        __syncwarp();
        if (lane == 0) {
            while (i > 0 && i >= r0) {
                int wcol = (j >> 4) - wb0;
                if (wcol < 0) break;
                unsigned word = tw[(i - r0) * 20 + wcol];
                for (;;) {
                    unsigned mv = (word >> ((j & 15) * 2)) & 3u;
                    if (mv == 2u) {           // left
                        j--;
                        if ((j & 15) == 15) break;   // crossed word boundary
                    } else {                  // diag or up
                        i--;
                        j -= (mv == 0u);
                        syl[i] = j;
                        break;
                    }
                }
            }
            sij[0] = i; sij[1] = j;
        }
        __syncwarp();
        i = sij[0]; j = sij[1];
        __syncwarp();
    }

    // write w_ts (= x_t) and w_vs (= y_t gathered at per-row path column)
    for (int n = lane; n < NN; n += 32) {
        out[BB + b * NN + n] = xt[b * NN + n];
        out[BB + BB * NN + b * NN + n] = yt[(size_t)b * MM + syl[n]];
    }
}

// ---------------- launch ----------------
extern "C" void kernel_launch(void* const* d_in, const int* in_sizes, int n_in,
                              void* d_out, int out_size) {
    const float* x = (const float*)d_in[0];   // [16,1024,64]
    const float* y = (const float*)d_in[1];   // [16,4096,64]
    const float* xt = (const float*)d_in[2];  // [16,1024]
    const float* yt = (const float*)d_in[3];  // [16,4096]
    float* out = (float*)d_out;               // [16] cost, [16,1024] w_ts, [16,1024] w_vs

    int totalRows = BB * NN + BB * MM;
    norms_kernel<<<(totalRows + 255) / 256, 256>>>(x, y);

    init_bnd_kernel<<<(BB * 3 * NN + 255) / 256, 256>>>();

    // 64 dtw CTAs (first wave, all resident) + 4096 gemm CTAs
    fused_kernel<<<BB * 4 + BB * (NN / 128) * (MM / 128), 256>>>(x, y);

    backtrack_kernel<<<BB, 32>>>(xt, yt, out);
}

// round 16
// speedup vs baseline: 1.2103x; 1.2103x over previous
#include <cuda_runtime.h>
#include <cuda_bf16.h>

// Problem constants: B=16, N=1024, M=4096, D=64
#define BB 16
#define NN 1024
#define MM 4096
#define DD 64
#define INF_BITS 0x7f800000u

// ---------------- device scratch (no cudaMalloc allowed) ----------------
__device__ float g_C[(size_t)BB * NN * MM];                 // 256 MB cost matrix
__device__ float g_x2[BB * NN];
__device__ float g_y2[BB * MM];
// packed moves: 4 cells per byte (2 bits each), row stride = MM/4 = 1024 bytes.
__device__ unsigned char g_mv[(size_t)BB * NN * (MM / 4) + 128];
// inter-CTA boundary handoff: 3 interfaces per batch, one word per row
__device__ unsigned g_bnd[BB][3][NN];
// per-CTA last-row argmin partials (4 CTAs per batch)
__device__ float g_pv[BB][4];
__device__ int g_pi[BB][4];

__device__ __forceinline__ unsigned ldcg_u32(const unsigned* p) {
    unsigned v;
    asm volatile("ld.global.cg.u32 %0, [%1];" : "=r"(v) : "l"(p));
    return v;
}
__device__ __forceinline__ void stcg_u32(unsigned* p, unsigned v) {
    asm volatile("st.global.cg.u32 [%0], %1;" :: "l"(p), "r"(v));
}
__device__ __forceinline__ void cpasync16(void* smem_dst, const void* gsrc) {
    unsigned saddr;
    asm("{ .reg .u64 t; cvta.to.shared.u64 t, %1; cvt.u32.u64 %0, t; }"
        : "=r"(saddr) : "l"(smem_dst));
    asm volatile("cp.async.cg.shared.global [%0], [%1], 16;"
                 :: "r"(saddr), "l"(gsrc) : "memory");
}
#define CP_COMMIT() asm volatile("cp.async.commit_group;" ::: "memory")
#define CP_WAIT6()  asm volatile("cp.async.wait_group 6;" ::: "memory")

// Packed f32x2 (Blackwell): two independent fp32 FMAs per instruction.
#define FMA_F32X2(d, a, b, c) \
    asm("fma.rn.f32x2 %0, %1, %2, %3;" : "=l"(d) : "l"(a), "l"(b), "l"(c))
#define PACK_F32X2(out, lo, hi) \
    asm("mov.b64 %0, {%1, %2};" : "=l"(out) : "r"(lo), "r"(hi))
#define UNPACK_F32X2(lo, hi, in) \
    asm("mov.b64 {%0, %1}, %2;" : "=r"(lo), "=r"(hi) : "l"(in))

// ---------------- kernel 0: row squared norms + boundary sentinel init ----------------
__global__ void norms_kernel(const float* __restrict__ x, const float* __restrict__ y) {
    int idx = blockIdx.x * blockDim.x + threadIdx.x;
    if (idx < BB * 3 * NN) ((unsigned*)g_bnd)[idx] = INF_BITS;
    const float* src;
    float* dst;
    if (idx < BB * NN) {
        src = x + (size_t)idx * DD;
        dst = g_x2 + idx;
    } else if (idx < BB * NN + BB * MM) {
        int k = idx - BB * NN;
        src = y + (size_t)k * DD;
        dst = g_y2 + k;
    } else {
        return;
    }
    float s = 0.f;
#pragma unroll
    for (int q = 0; q < DD / 4; q++) {
        float4 v = *(const float4*)(src + q * 4);
        s += v.x * v.x + v.y * v.y + v.z * v.z + v.w * v.w;
    }
    *dst = s;
}

// ---------------- kernel 1: C = x2 + y2 - 2 * x @ y^T (f32x2 packed FMA) ----------------
__global__ void __launch_bounds__(256, 2) gemm_kernel(const float* __restrict__ x,
                                                      const float* __restrict__ y) {
    __shared__ float Xs[32][128];
    __shared__ float Ys[32][128];
    int b = blockIdx.z;
    int i0 = blockIdx.y * 128;
    int j0 = blockIdx.x * 128;
    const float* xb = x + (size_t)b * NN * DD;
    const float* yb = y + (size_t)b * MM * DD;
    int tid = threadIdx.x;
    int txc = tid & 15, tyc = tid >> 4;

    // acc2[mm][q] holds columns (2q, 2q+1) of the 8-wide n-tile, packed f32x2
    unsigned long long acc2[8][4];
#pragma unroll
    for (int a = 0; a < 8; a++)
#pragma unroll
        for (int c = 0; c < 4; c++) acc2[a][c] = 0ull;

#pragma unroll
    for (int kt = 0; kt < DD; kt += 32) {
#pragma unroll
        for (int p = 0; p < 4; p++) {
            int idx = tid + p * 256;
            int q = idx & 7;
            int r = idx >> 3;
            float4 xv = *(const float4*)(xb + (size_t)(i0 + r) * DD + kt + q * 4);
            Xs[q * 4 + 0][r] = xv.x;
            Xs[q * 4 + 1][r] = xv.y;
            Xs[q * 4 + 2][r] = xv.z;
            Xs[q * 4 + 3][r] = xv.w;
            float4 yv = *(const float4*)(yb + (size_t)(j0 + r) * DD + kt + q * 4);
            Ys[q * 4 + 0][r] = yv.x;
            Ys[q * 4 + 1][r] = yv.y;
            Ys[q * 4 + 2][r] = yv.z;
            Ys[q * 4 + 3][r] = yv.w;
        }
        __syncthreads();
#pragma unroll
        for (int kk = 0; kk < 32; kk++) {
            float xf[8];
            *(float4*)&xf[0] = *(const float4*)&Xs[kk][tyc * 4];
            *(float4*)&xf[4] = *(const float4*)&Xs[kk][64 + tyc * 4];
            // y pairs arrive pre-packed from 128-bit smem loads
            ulonglong2 ya = *(const ulonglong2*)&Ys[kk][txc * 4];
            ulonglong2 yb2 = *(const ulonglong2*)&Ys[kk][64 + txc * 4];
            unsigned long long yp0 = ya.x, yp1 = ya.y, yp2 = yb2.x, yp3 = yb2.y;
#pragma unroll
            for (int mm = 0; mm < 8; mm++) {
                unsigned long long xd;
                unsigned xb_ = __float_as_uint(xf[mm]);
                PACK_F32X2(xd, xb_, xb_);
                FMA_F32X2(acc2[mm][0], xd, yp0, acc2[mm][0]);
                FMA_F32X2(acc2[mm][1], xd, yp1, acc2[mm][1]);
                FMA_F32X2(acc2[mm][2], xd, yp2, acc2[mm][2]);
                FMA_F32X2(acc2[mm][3], xd, yp3, acc2[mm][3]);
            }
        }
        __syncthreads();
    }

    float y2v[8];
    *(float4*)&y2v[0] = *(const float4*)(g_y2 + b * MM + j0 + txc * 4);
    *(float4*)&y2v[4] = *(const float4*)(g_y2 + b * MM + j0 + 64 + txc * 4);
#pragma unroll
    for (int mm = 0; mm < 8; mm++) {
        int row = i0 + ((mm < 4) ? (tyc * 4 + mm) : (64 + tyc * 4 + mm - 4));
        float x2v = g_x2[b * NN + row];
        float* crow = g_C + ((size_t)b * NN + row) * MM + j0;
        float o[8];
#pragma unroll
        for (int q = 0; q < 4; q++) {
            unsigned lo, hi;
            UNPACK_F32X2(lo, hi, acc2[mm][q]);
            o[2 * q] = __uint_as_float(lo);
            o[2 * q + 1] = __uint_as_float(hi);
        }
        float4 v0, v1;
        v0.x = x2v + y2v[0] - 2.f * o[0];
        v0.y = x2v + y2v[1] - 2.f * o[1];
        v0.z = x2v + y2v[2] - 2.f * o[2];
        v0.w = x2v + y2v[3] - 2.f * o[3];
        v1.x = x2v + y2v[4] - 2.f * o[4];
        v1.y = x2v + y2v[5] - 2.f * o[5];
        v1.z = x2v + y2v[6] - 2.f * o[6];
        v1.w = x2v + y2v[7] - 2.f * o[7];
        *(float4*)(crow + txc * 4) = v0;
        *(float4*)(crow + 64 + txc * 4) = v1;
    }
}

// ---------------- kernel 2: dataflow subsequence-DTW forward DP ----------------
// (byte-identical to the passing R11 version: 4 CTAs/batch, 8 warps/CTA,
// cp.async 6-deep C-row ring, arbiter-aligned SPSC boundary rings with
// producer back-pressure, eager inter-CTA gmem boundary loads)
__global__ void __launch_bounds__(256, 1) dtw_kernel() {
    const unsigned FULL = 0xffffffffu;
    const float INF = __uint_as_float(INF_BITS);
    int cta = blockIdx.x;
    int b = cta >> 2, r = cta & 3;
    int t = threadIdx.x, lane = t & 31, w = t >> 5;
    int chunk = 7 - w;                          // 0 = leftmost chunk of this CTA
    int colbase = r * 1024 + chunk * 128 + lane * 4;
    const float* Cp = g_C + (size_t)b * NN * MM + colbase;
    unsigned char* mvp = g_mv + (size_t)b * NN * (MM / 4) + (colbase >> 2);

    __shared__ volatile unsigned sB[7][128];    // sB[w]: written by warp w+1, read by warp w
    __shared__ float4 sring[8][8][32];          // per-warp 8-deep C-row ring (512B/row)
    __shared__ float sRv[8];
    __shared__ int sRi[8];
    for (int q = t; q < 7 * 128; q += 256) ((volatile unsigned*)sB)[q] = INF_BITS;
    __syncthreads();

    const bool gin = (w == 7 && r > 0);         // leftmost chunk consumes gmem boundary
    const bool gout = (w == 0 && r < 3);        // rightmost chunk produces gmem boundary
    const unsigned* gbi = gin ? &g_bnd[b][r - 1][0] : (const unsigned*)0;
    unsigned* gbo = gout ? &g_bnd[b][r][0] : (unsigned*)0;

    // ---- cp.async prologue: rows 0..5 in flight ----
#pragma unroll
    for (int k = 0; k < 6; k++) {
        cpasync16(&sring[w][k][lane], Cp + (size_t)k * MM);
        CP_COMMIT();
    }
    cpasync16(&sring[w][6][lane], Cp + 6 * (size_t)MM);
    CP_COMMIT();
    CP_WAIT6();

    // ---- row 0: D = C[0,:] ----
    float4 c4 = sring[w][0][lane];
    float pd[4] = {c4.x, c4.y, c4.z, c4.w};

    // acquire left boundary of row 0 (becomes prevB for row 1)
    float B = INF;
    if (w < 7) {
        unsigned vb;
        do { vb = sB[w][0]; } while (vb == INF_BITS);
        if (lane == 0) sB[w][0] = INF_BITS;
        B = __uint_as_float(vb);
    } else if (gin) {
        unsigned vb;
        do { vb = ldcg_u32(gbi + 0); } while (vb == INF_BITS);
        B = __uint_as_float(vb);
    }
    float prevB = B;

    // publish D[0][chunk_end]
    {
        float dend = __shfl_sync(FULL, pd[3], 31);
        if (lane == 31) {
            unsigned ob = __float_as_uint(dend);
            if (w > 0) sB[w - 1][0] = ob;
            else if (gout) stcg_u32(gbo + 0, ob);
        }
    }

    for (int i = 1; i < NN; i++) {
        int q = i + 6;
        if (q < NN) cpasync16(&sring[w][q & 7][lane], Cp + (size_t)q * MM);
        CP_COMMIT();
        CP_WAIT6();                              // rows <= i ready

        // eager inter-CTA boundary load: latency overlaps the scan below
        unsigned vb0 = INF_BITS;
        if (gin && lane == 0) vb0 = ldcg_u32(gbi + i);

        float4 cc = sring[w][i & 7][lane];
        float c[4] = {cc.x, cc.y, cc.z, cc.w};

        // pl = D[i-1][j-1]
        float pl0 = __shfl_up_sync(FULL, pd[3], 1);
        if (lane == 0) pl0 = prevB;
        float a[4];
        a[0] = fminf(pd[0], pl0) + c[0];
#pragma unroll
        for (int k = 1; k < 4; k++) a[k] = fminf(pd[k], pd[k - 1]) + c[k];

        // thread-local min-plus compose
        float Sl = c[0], Ml = a[0];
#pragma unroll
        for (int k = 1; k < 4; k++) {
            Sl += c[k];
            Ml = fminf(Ml + c[k], a[k]);
        }
        // warp inclusive min-plus pair scan (speculative w.r.t. boundary B)
        float iS = Sl, iM = Ml;
#pragma unroll
        for (int off = 1; off < 32; off <<= 1) {
            float oS = __shfl_up_sync(FULL, iS, off);
            float oM = __shfl_up_sync(FULL, iM, off);
            if (lane >= off) { iM = fminf(oM + iS, iM); iS = oS + iS; }
        }
        float eS = __shfl_up_sync(FULL, iS, 1);
        float eM = __shfl_up_sync(FULL, iM, 1);
        if (lane == 0) { eS = 0.f; eM = INF; }

        // acquire left boundary B = D[i][chunk_start-1]
        B = INF;
        if (w < 7) {
            unsigned vb;
            volatile unsigned* sl = &sB[w][i & 127];
            do { vb = *sl; } while (vb == INF_BITS);
            if (lane == 0) *sl = INF_BITS;
            B = __uint_as_float(vb);
        } else if (gin) {
            if (lane == 0) {
                while (vb0 == INF_BITS) vb0 = ldcg_u32(gbi + i);
            }
            vb0 = __shfl_sync(FULL, vb0, 0);
            B = __uint_as_float(vb0);
        }

        // publish own boundary ASAP (lane 31 holds the chunk totals).
        if (lane == 31) {
            float dend = fminf(B + iS, iM);
            unsigned ob = __float_as_uint(dend);
            if (w > 0) {
                volatile unsigned* so = &sB[w - 1][i & 127];
                while (*so != INF_BITS) {}       // back-pressure (depth-128 ring)
                *so = ob;
            } else if (gout) {
                stcg_u32(gbo + i, ob);
            }
        }

        // finalize with the carry applied
        float M_ex = fminf(B + eS, eM);         // == D[i][lane_start-1]
        float nd[4];
        float Mr = M_ex;
#pragma unroll
        for (int k = 0; k < 4; k++) {
            Mr = fminf(Mr + c[k], a[k]);
            nd[k] = Mr;
        }
        // move codes (dd = D[i-1][j-1], du = D[i-1][j], dl = D[i][j-1])
        unsigned pk = 0;
        float dl = M_ex, dd = pl0;
#pragma unroll
        for (int k = 0; k < 4; k++) {
            float du = pd[k];
            unsigned m = (du <= dl) ? 1u : 2u;
            if (dd <= du && dd <= dl) m = 0u;
            pk |= m << (2 * k);
            dd = du;
            dl = nd[k];
        }
        mvp[(size_t)i * (MM / 4)] = (unsigned char)pk;

        prevB = B;
#pragma unroll
        for (int k = 0; k < 4; k++) pd[k] = nd[k];
    }

    // ---- per-CTA argmin of last row (first index on exact ties) ----
    float bv = pd[0];
    int bi = colbase;
#pragma unroll
    for (int k = 1; k < 4; k++)
        if (pd[k] < bv) { bv = pd[k]; bi = colbase + k; }
#pragma unroll
    for (int off = 16; off > 0; off >>= 1) {
        float ov = __shfl_down_sync(FULL, bv, off);
        int oi = __shfl_down_sync(FULL, bi, off);
        if (ov < bv || (ov == bv && oi < bi)) { bv = ov; bi = oi; }
    }
    if (lane == 0) { sRv[w] = bv; sRi[w] = bi; }
    __syncthreads();
    if (t == 0) {
        float v = sRv[0]; int ix = sRi[0];
#pragma unroll
        for (int qq = 1; qq < 8; qq++)
            if (sRv[qq] < v || (sRv[qq] == v && sRi[qq] < ix)) { v = sRv[qq]; ix = sRi[qq]; }
        g_pv[b][r] = v;
        g_pi[b][r] = ix;
    }
}

// ---------------- kernel 3: backtrack over packed moves ----------------
// One warp per batch. 64-row x 20-word smem tile (guard row at index 0).
// lane0 walks it; the word for row i-1 is prefetched speculatively before
// decoding row i, hiding the LDS latency behind the decode.
__global__ void __launch_bounds__(32) backtrack_kernel(const float* __restrict__ xt,
                                                       const float* __restrict__ yt,
                                                       float* __restrict__ out) {
    int b = blockIdx.x;
    int lane = threadIdx.x;
    __shared__ uint4 tile4[65][5];    // row 0 = guard; rows 1..64 = data
    __shared__ int syl[NN];
    __shared__ int sij[2];
    const unsigned* tw = (const unsigned*)tile4;   // 20 words per tile row
    const unsigned char* mvb = g_mv + (size_t)b * NN * (MM / 4);

    // final argmin across the 4 CTA partials (first global index on ties)
    if (lane == 0) {
        float bv = g_pv[b][0]; int bi = g_pi[b][0];
#pragma unroll
        for (int q = 1; q < 4; q++) {
            float v = g_pv[b][q]; int ix = g_pi[b][q];
            if (v < bv || (v == bv && ix < bi)) { bv = v; bi = ix; }
        }
        out[b] = bv;                  // dtw_cost
        syl[NN - 1] = bi;
        sij[0] = NN - 1; sij[1] = bi;
    }
    __syncwarp();
    int i = sij[0], j = sij[1];

    while (i > 0) {
        int r0 = i - 63; if (r0 < 1) r0 = 1;
        int wb0 = (j >> 4) - 15; if (wb0 < 0) wb0 = 0;
        wb0 &= ~3;                    // 16B-align the word window
#pragma unroll
        for (int p = 0; p < 10; p++) {
            int idx = lane + p * 32;  // 0..319
            int rr = idx / 5, q = idx - rr * 5;
            tile4[rr + 1][q] = *(const uint4*)(mvb + (size_t)(r0 + rr) * (MM / 4) + wb0 * 4 + q * 16);
        }
        __syncwarp();
        if (lane == 0) {
            int wcol = (j >> 4) - wb0;
            unsigned w0 = tw[(i - r0 + 1) * 20 + wcol];
            while (i > 0 && i >= r0 && wcol >= 0) {
                unsigned wup = tw[(i - r0) * 20 + wcol];  // speculative: row i-1
                unsigned mv;
                for (;;) {
                    mv = (w0 >> ((j & 15) * 2)) & 3u;
                    if (mv != 2u) break;
                    j--;                                  // left
                    if ((j & 15) == 15) {                 // crossed word boundary
                        wcol--;
                        if (wcol < 0) break;
                        w0 = tw[(i - r0 + 1) * 20 + wcol];
                        wup = tw[(i - r0) * 20 + wcol];
                    }
                }
                if (wcol < 0) break;
                // mv == 0 (diag) or 1 (up)
                i--;
                j -= (mv == 0u);
                syl[i] = j;
                if (mv == 0u && (j & 15) == 15) {         // diag crossed word boundary
                    wcol--;
                    if (wcol < 0) break;
                    w0 = tw[(i - r0 + 1) * 20 + wcol];
                } else {
                    w0 = wup;
                }
            }
            sij[0] = i; sij[1] = j;
        }
        __syncwarp();
        i = sij[0]; j = sij[1];
        __syncwarp();
    }

    // write w_ts (= x_t) and w_vs (= y_t gathered at per-row path column)
    for (int n = lane; n < NN; n += 32) {
        out[BB + b * NN + n] = xt[b * NN + n];
        out[BB + BB * NN + b * NN + n] = yt[(size_t)b * MM + syl[n]];
    }
}

// ---------------- launch ----------------
extern "C" void kernel_launch(void* const* d_in, const int* in_sizes, int n_in,
                              void* d_out, int out_size) {
    const float* x = (const float*)d_in[0];   // [16,1024,64]
    const float* y = (const float*)d_in[1];   // [16,4096,64]
    const float* xt = (const float*)d_in[2];  // [16,1024]
    const float* yt = (const float*)d_in[3];  // [16,4096]
    float* out = (float*)d_out;               // [16] cost, [16,1024] w_ts, [16,1024] w_vs

    int totalRows = BB * NN + BB * MM;        // 81920 >= BB*3*NN, covers bnd init too
    norms_kernel<<<(totalRows + 255) / 256, 256>>>(x, y);

    dim3 gg(MM / 128, NN / 128, BB);
    gemm_kernel<<<gg, 256>>>(x, y);

    dtw_kernel<<<BB * 4, 256>>>();

    backtrack_kernel<<<BB, 32>>>(xt, yt, out);
}